// round 8
// baseline (speedup 1.0000x reference)
#include <cuda_runtime.h>
#include <cstddef>

// Problem constants
constexpr int NB = 32;      // batch
constexpr int NS = 2048;    // sequence
constexpr int ND = 512;     // model dim
constexpr int NF = 512;     // dff
constexpr int CH = 128;     // chunks per batch
constexpr int ROWS = NS / CH;   // 16 rows per chunk (32 KB in smem)
constexpr int SL = ND / CH;     // 4-wide slices for B1/B2/C
#define INV_SQRT_DFF 0.044194173824159216f  // 1/sqrt(512)

// Scratch (device globals; statically zero-initialized, no allocation)
__device__ float g_xwp[CH * NB * ND];   // xw partials per chunk
__device__ float g_xw[NB * ND];
__device__ float g_wsump[CH];
__device__ float g_kw[NB * NF];
__device__ float g_cp[NB * CH];
__device__ float g_u[NB * ND];
__device__ float g_xtp[CH * NB * ND];   // xt partials
__device__ float g_Tp[CH * NB];
__device__ float g_T[NB];
__device__ float g_xt[NB * ND];
__device__ int   g_cnt1[NB], g_cnt2[NB], g_cnt3[NB], g_cnt4[NB], g_fin[NB];

// per-batch spin barrier (intra-batch only -> deadlock-free at any occupancy)
#define BATCH_BAR(CNT)                                             \
    do {                                                           \
        __threadfence();                                           \
        if (tid == 0) {                                            \
            atomicAdd(&CNT[b], 1);                                 \
            while (((volatile int*)CNT)[b] < CH) __nanosleep(64);  \
        }                                                          \
        __syncthreads();                                           \
    } while (0)

// ---------------------------------------------------------------------------
// Fused per-batch pipeline; x chunk pinned in SMEM so x crosses DRAM ONCE.
// grid = NB*CH (batch-major), 256 threads.
//   A : load x chunk -> smem, fused xw partial; wsum chunk partial
//   B1: reduce xw slice (4 d)
//   B2: kw slice (4 f) + c partial
//   C : u slice (4 d)
//   D : ta + xt/T partials from SMEM-resident chunk
// ---------------------------------------------------------------------------
__global__ __launch_bounds__(256) void k_fused(
    const float* __restrict__ x,  const float* __restrict__ Wq,
    const float* __restrict__ bq, const float* __restrict__ Wk,
    const float* __restrict__ bk, const float* __restrict__ Wt,
    const float* __restrict__ bt) {
    const int bid = blockIdx.x;
    const int b = bid >> 7;          // batch
    const int c = bid & 127;         // chunk / slice index
    const int tid = threadIdx.x, warp = tid >> 5, lane = tid & 31;
    const int s0 = c * ROWS;

    __shared__ float4 xs4[ROWS * 128];     // 32 KB: the x chunk
    __shared__ float4 s_redA[2 * 128];     // 4 KB stage-A cross-group reduce
    __shared__ float  s_vec[ND];           // xw/kw/u broadcast (2 KB)
    __shared__ float  s_red[512];          // slice reduce (2 KB)
    __shared__ float  s_cp[CH];            // 512 B
    __shared__ float  s_ta[ROWS];
    __shared__ float  s_wt[ROWS];
    __shared__ float  s_kw4[SL];
    __shared__ float  s_scalar;

    // ---------------- Stage A: smem-load + fused xw partial ----------------
    if (tid < ROWS) s_wt[tid] = Wt[s0 + tid];
    __syncthreads();

    if (warp == 0) {   // wsum chunk partial (identical across batches: benign)
        float w = (lane < ROWS) ? s_wt[lane] : 0.f;
#pragma unroll
        for (int off = 16; off; off >>= 1) w += __shfl_xor_sync(0xffffffffu, w, off);
        if (lane == 0) g_wsump[c] = w;
    }

    {
        // thread t covers col4 = t&127, rows (t>>7) + 2i, i=0..7
        const float4* xg = (const float4*)x + ((size_t)b * NS + s0) * 128;
        float4 acc = {0.f, 0.f, 0.f, 0.f};
#pragma unroll
        for (int i = 0; i < 8; i++) {
            const int idx = tid + 256 * i;
            const float4 v = xg[idx];
            const float wt = s_wt[idx >> 7];
            acc.x += wt * v.x; acc.y += wt * v.y;
            acc.z += wt * v.z; acc.w += wt * v.w;
            xs4[idx] = v;
        }
        s_redA[(tid >> 7) * 128 + (tid & 127)] = acc;
        __syncthreads();

        if (tid < 128) {
            float4 a = s_redA[tid], bb = s_redA[128 + tid];
            float4 r = {a.x + bb.x, a.y + bb.y, a.z + bb.z, a.w + bb.w};
            ((float4*)g_xwp)[((size_t)c * NB + b) * 128 + tid] = r;
        }
    }
    BATCH_BAR(g_cnt1);

    // ---------------- Stage B1: reduce xw slice (d in [c*4, c*4+4)) --------
    {
        const int dl = tid & 3, g = tid >> 2;      // g: 0..63, 2 chunks each
        float v = __ldcg(&g_xwp[((size_t)g        * NB + b) * ND + c * SL + dl])
                + __ldcg(&g_xwp[((size_t)(g + 64) * NB + b) * ND + c * SL + dl]);
        s_red[g * SL + dl] = v;
        __syncthreads();
        if (tid < SL) {
            float xw = 0.f;
#pragma unroll
            for (int g2 = 0; g2 < 64; g2++) xw += s_red[g2 * SL + tid];
            g_xw[b * ND + c * SL + tid] = xw;
        }
    }
    BATCH_BAR(g_cnt2);

    // ---------------- Stage B2: kw slice (f in [c*4, c*4+4)) ---------------
    {
        s_vec[tid]       = __ldcg(&g_xw[b * ND + tid]);
        s_vec[tid + 256] = __ldcg(&g_xw[b * ND + tid + 256]);
        if (tid < CH) s_red[tid] = __ldcg(&g_wsump[tid]);   // parallel L2
        __syncthreads();
        if (tid == 0) {
            float ws = 0.f;
#pragma unroll
            for (int c2 = 0; c2 < CH; c2++) ws += s_red[c2];  // smem-only chain
            s_scalar = ws;
        }
        __syncthreads();

        const float wsum = s_scalar;
        if (warp < SL) {
            const int f = c * SL + warp;
            const float* wk = Wk + (size_t)f * ND;
            float acc = 0.f;
#pragma unroll
            for (int q = 0; q < 16; q++)
                acc += wk[lane + 32 * q] * s_vec[lane + 32 * q];
#pragma unroll
            for (int off = 16; off; off >>= 1)
                acc += __shfl_xor_sync(0xffffffffu, acc, off);
            if (lane == 0) {
                const float kwv = acc + bk[f] * wsum;
                g_kw[b * NF + f] = kwv;
                s_kw4[warp] = bq[f] * kwv;
            }
        }
        __syncthreads();
        if (tid == 0) {
            float cp = 0.f;
#pragma unroll
            for (int i = 0; i < SL; i++) cp += s_kw4[i];
            g_cp[b * CH + c] = cp;
        }
    }
    BATCH_BAR(g_cnt3);

    // ---------------- Stage C: u slice (d in [c*4, c*4+4)) -----------------
    {
        s_vec[tid]       = __ldcg(&g_kw[b * NF + tid]);
        s_vec[tid + 256] = __ldcg(&g_kw[b * NF + tid + 256]);
        __syncthreads();

        const int dl = tid & 3, fg = tid >> 2;     // fg: 0..63, 8 f each
        float acc = 0.f;
#pragma unroll
        for (int i = 0; i < 8; i++) {
            const int f = fg * 8 + i;
            acc += Wq[(size_t)f * ND + c * SL + dl] * s_vec[f];
        }
        __syncthreads();
        s_red[fg * SL + dl] = acc;
        __syncthreads();
        if (tid < SL) {
            float u = 0.f;
#pragma unroll
            for (int g2 = 0; g2 < 64; g2++) u += s_red[g2 * SL + tid];
            g_u[b * ND + c * SL + tid] = u;
        }
    }
    BATCH_BAR(g_cnt4);

    // ---------------- Stage D: ta + xt/T partials from SMEM ----------------
    {
        s_vec[tid]       = __ldcg(&g_u[b * ND + tid]);
        s_vec[tid + 256] = __ldcg(&g_u[b * ND + tid + 256]);
        if (tid < CH) s_cp[tid] = __ldcg(&g_cp[b * CH + tid]);  // parallel L2
        __syncthreads();
        if (tid == 0) {
            float cb = 0.f;
#pragma unroll
            for (int k = 0; k < CH; k++) cb += s_cp[k];   // smem-only chain
            s_scalar = cb;
        }
        __syncthreads();

        const float cb = s_scalar;
        const float btv = bt[0];

        // phase 1: ta[r] for 16 rows (8 warps x 2 rows)
        const float4* u4p = (const float4*)s_vec;
        float4 u4[4];
#pragma unroll
        for (int q = 0; q < 4; q++) u4[q] = u4p[lane + 32 * q];

#pragma unroll
        for (int rr = 0; rr < 2; rr++) {
            const int r = warp * 2 + rr;
            float dot = 0.f;
#pragma unroll
            for (int q = 0; q < 4; q++) {
                const float4 xv = xs4[r * 128 + lane + 32 * q];
                dot += xv.x * u4[q].x + xv.y * u4[q].y +
                       xv.z * u4[q].z + xv.w * u4[q].w;
            }
#pragma unroll
            for (int off = 16; off; off >>= 1)
                dot += __shfl_xor_sync(0xffffffffu, dot, off);
            if (lane == 0) s_ta[r] = (dot + cb) * INV_SQRT_DFF + btv;
        }
        __syncthreads();

        // phase 2: xt[d] = sum_r ta[r]*x[r][d]; each thread 2 d-columns
        const float* xsf = (const float*)xs4;
        float a0 = 0.f, a1 = 0.f;
#pragma unroll
        for (int r = 0; r < ROWS; r++) {
            const float ta = s_ta[r];
            a0 += ta * xsf[r * ND + tid];
            a1 += ta * xsf[r * ND + tid + 256];
        }
        float* dst = g_xtp + ((size_t)c * NB + b) * ND;
        dst[tid] = a0;
        dst[tid + 256] = a1;

        if (warp == 0) {   // T partial
            float t = (lane < ROWS) ? s_ta[lane] : 0.f;
#pragma unroll
            for (int off = 16; off; off >>= 1)
                t += __shfl_xor_sync(0xffffffffu, t, off);
            if (lane == 0) g_Tp[c * NB + b] = t;
        }
    }

    // ---------------- Reset counters for next graph replay ------------------
    __threadfence();
    if (tid == 0) {
        const int old = atomicAdd(&g_fin[b], 1);
        if (old == CH - 1) {       // last arriver: nobody spins anymore
            g_cnt1[b] = 0; g_cnt2[b] = 0;
            g_cnt3[b] = 0; g_cnt4[b] = 0;
            g_fin[b] = 0;
        }
    }
}

// ---------------------------------------------------------------------------
// Reduce xt partials + T partials. grid 32, 512 threads
// ---------------------------------------------------------------------------
__global__ __launch_bounds__(512) void k_red2() {
    const int i = blockIdx.x * 512 + threadIdx.x;
    float v = 0.f;
#pragma unroll
    for (int c = 0; c < CH; c++) v += g_xtp[(size_t)c * NB * ND + i];
    g_xt[i] = v;

    if (blockIdx.x == 0 && threadIdx.x < NB) {
        float t = 0.f;
#pragma unroll
        for (int c = 0; c < CH; c++) t += g_Tp[c * NB + threadIdx.x];
        g_T[threadIdx.x] = t;
    }
}

// ---------------------------------------------------------------------------
// latent[b,f] = Wv[f,:].xt[b,:] + bv[f]*T[b]
// Batch-tiled: 32 blocks, each owns 16 f-rows of Wv in smem (Wv read ONCE).
// ---------------------------------------------------------------------------
__global__ __launch_bounds__(256) void k_out(const float* __restrict__ Wv,
                                             const float* __restrict__ bv,
                                             float* __restrict__ out) {
    const int f0 = blockIdx.x * 16;
    const int tid = threadIdx.x, warp = tid >> 5, lane = tid & 31;

    __shared__ float s_wv[16 * ND];     // 32 KB
    __shared__ float s_T[NB];

    {
        const float4* src = (const float4*)(Wv + (size_t)f0 * ND);
        float4* d4 = (float4*)s_wv;
#pragma unroll
        for (int i = 0; i < 8; i++) d4[tid + 256 * i] = src[tid + 256 * i];
    }
    if (tid < NB) s_T[tid] = g_T[tid];
    __syncthreads();

#pragma unroll
    for (int j = 0; j < 2; j++) {
        const int fl = warp * 2 + j;
        const int f  = f0 + fl;
        const float4* wrow = (const float4*)(s_wv + fl * ND);
        float4 w4[4];
#pragma unroll
        for (int q = 0; q < 4; q++) w4[q] = wrow[lane + 32 * q];
        const float bvf = bv[f];

#pragma unroll 4
        for (int b = 0; b < NB; b++) {
            const float4* xt4 = (const float4*)(g_xt + b * ND);
            float dot = 0.f;
#pragma unroll
            for (int q = 0; q < 4; q++) {
                float4 xv = xt4[lane + 32 * q];
                dot += w4[q].x * xv.x + w4[q].y * xv.y +
                       w4[q].z * xv.z + w4[q].w * xv.w;
            }
#pragma unroll
            for (int off = 16; off; off >>= 1)
                dot += __shfl_xor_sync(0xffffffffu, dot, off);
            if (lane == 0) out[b * NF + f] = dot + bvf * s_T[b];
        }
    }
}

// ---------------------------------------------------------------------------
extern "C" void kernel_launch(void* const* d_in, const int* in_sizes, int n_in,
                              void* d_out, int out_size) {
    const float* x  = (const float*)d_in[0];
    const float* Wq = (const float*)d_in[1];
    const float* bq = (const float*)d_in[2];
    const float* Wk = (const float*)d_in[3];
    const float* bk = (const float*)d_in[4];
    const float* Wv = (const float*)d_in[5];
    const float* bv = (const float*)d_in[6];
    const float* Wt = (const float*)d_in[7];
    const float* bt = (const float*)d_in[8];
    float* out = (float*)d_out;

    k_fused<<<NB * CH, 256>>>(x, Wq, bq, Wk, bk, Wt, bt);
    k_red2 <<<32, 512>>>();
    k_out  <<<32, 256>>>(Wv, bv, out);
}

// round 9
// speedup vs baseline: 1.5787x; 1.5787x over previous
#include <cuda_runtime.h>
#include <cstddef>

// Problem constants
constexpr int NB = 32;      // batch
constexpr int NS = 2048;    // sequence
constexpr int ND = 512;     // model dim
constexpr int NF = 512;     // dff
constexpr int CH = 16;      // chunks per batch -> 512 blocks total (ONE wave)
constexpr int ROWS = NS / CH;   // 128 rows per chunk
constexpr int SL = ND / CH;     // 32-wide slices for B1/B2/C
constexpr int NW = 8;       // warps per block
#define INV_SQRT_DFF 0.044194173824159216f  // 1/sqrt(512)

// Scratch (device globals; statically zero-initialized, no allocation)
__device__ float g_xwp[CH * NB * ND];   // xw partials per chunk (1 MB)
__device__ float g_xw[NB * ND];
__device__ float g_wsump[CH];
__device__ float g_kw[NB * NF];
__device__ float g_cp[NB * CH];
__device__ float g_u[NB * ND];
__device__ float g_xtp[CH * NB * ND];   // xt partials (1 MB)
__device__ float g_Tp[CH * NB];
__device__ float g_T[NB];
__device__ float g_xt[NB * ND];
__device__ int   g_cnt1[NB], g_cnt2[NB], g_cnt3[NB], g_cnt4[NB], g_fin[NB];

// per-batch spin barrier (intra-batch only; whole grid co-resident -> cheap)
#define BATCH_BAR(CNT)                                             \
    do {                                                           \
        __threadfence();                                           \
        if (tid == 0) {                                            \
            atomicAdd(&CNT[b], 1);                                 \
            while (((volatile int*)CNT)[b] < CH) __nanosleep(64);  \
        }                                                          \
        __syncthreads();                                           \
    } while (0)

// ---------------------------------------------------------------------------
// Fused per-batch pipeline. grid = NB*CH = 512 (batch-major), 256 threads.
//   A : xw partial from own x chunk (DRAM pass 1) + wsum chunk partial
//   B1: reduce xw slice (32 d)
//   B2: kw slice (32 f) + c partial
//   C : u slice (32 d)
//   D : pass2 on own x chunk (DRAM pass 2) -> xt/T partials
// ---------------------------------------------------------------------------
__global__ __launch_bounds__(256) void k_fused(
    const float* __restrict__ x,  const float* __restrict__ Wq,
    const float* __restrict__ bq, const float* __restrict__ Wk,
    const float* __restrict__ bk, const float* __restrict__ Wt,
    const float* __restrict__ bt) {
    const int bid = blockIdx.x;
    const int b = bid >> 4;          // batch
    const int c = bid & 15;          // chunk / slice index
    const int tid = threadIdx.x, warp = tid >> 5, lane = tid & 31;
    const int s0 = c * ROWS;

    __shared__ float  s_wt[ROWS];        // 512 B
    __shared__ float4 s4[NW * 128];      // 16 KB reduce buffer (A and D)
    __shared__ float  s_vec[ND];         // 2 KB broadcast
    __shared__ float  s_red[256];        // 1 KB
    __shared__ float  s_kw32[SL];        // 128 B
    __shared__ float  s_cp[CH];          // 64 B
    __shared__ float  s_T[NW];
    __shared__ float  s_scalar;

    // ---------------- Stage A: xw partial + wsum chunk partial -------------
    if (tid < ROWS) s_wt[tid] = Wt[s0 + tid];
    __syncthreads();

    if (warp == 0) {   // identical across batches: benign redundant store
        float w = s_wt[lane] + s_wt[lane + 32] + s_wt[lane + 64] + s_wt[lane + 96];
#pragma unroll
        for (int off = 16; off; off >>= 1) w += __shfl_xor_sync(0xffffffffu, w, off);
        if (lane == 0) g_wsump[c] = w;
    }

    {
        float4 acc[4] = {{0,0,0,0},{0,0,0,0},{0,0,0,0},{0,0,0,0}};
#pragma unroll 2
        for (int r = warp; r < ROWS; r += NW) {
            const float4* xp = (const float4*)x + ((size_t)b * NS + s0 + r) * (ND / 4);
            const float wt = s_wt[r];
#pragma unroll
            for (int j = 0; j < 4; j++) {
                float4 v = xp[32 * j + lane];
                acc[j].x += wt * v.x; acc[j].y += wt * v.y;
                acc[j].z += wt * v.z; acc[j].w += wt * v.w;
            }
        }
#pragma unroll
        for (int j = 0; j < 4; j++) s4[warp * 128 + 32 * j + lane] = acc[j];
        __syncthreads();

        const float* s = (const float*)s4;
        float v0 = 0.f, v1 = 0.f;
#pragma unroll
        for (int w = 0; w < NW; w++) {
            v0 += s[w * 512 + tid];
            v1 += s[w * 512 + tid + 256];
        }
        float* dst = g_xwp + ((size_t)c * NB + b) * ND;
        dst[tid] = v0;
        dst[tid + 256] = v1;
    }
    BATCH_BAR(g_cnt1);

    // ---------------- Stage B1: reduce xw slice (d in [c*32, c*32+32)) -----
    {
        const int dl = tid & 31, g = tid >> 5;      // g: 0..7, 2 chunks each
        float v = __ldcg(&g_xwp[((size_t)(g * 2)     * NB + b) * ND + c * SL + dl])
                + __ldcg(&g_xwp[((size_t)(g * 2 + 1) * NB + b) * ND + c * SL + dl]);
        s_red[g * SL + dl] = v;
        __syncthreads();
        if (tid < SL) {
            float xw = 0.f;
#pragma unroll
            for (int g2 = 0; g2 < 8; g2++) xw += s_red[g2 * SL + tid];
            g_xw[b * ND + c * SL + tid] = xw;
        }
    }
    BATCH_BAR(g_cnt2);

    // ---------------- Stage B2: kw slice (f in [c*32, c*32+32)) ------------
    {
        s_vec[tid]       = __ldcg(&g_xw[b * ND + tid]);
        s_vec[tid + 256] = __ldcg(&g_xw[b * ND + tid + 256]);
        if (tid < CH) s_red[tid] = __ldcg(&g_wsump[tid]);   // parallel L2
        __syncthreads();
        if (tid == 0) {
            float ws = 0.f;
#pragma unroll
            for (int c2 = 0; c2 < CH; c2++) ws += s_red[c2];  // smem-only chain
            s_scalar = ws;
        }
        __syncthreads();

        const float wsum = s_scalar;
#pragma unroll
        for (int j = 0; j < 4; j++) {
            const int f = c * SL + warp * 4 + j;
            const float* wk = Wk + (size_t)f * ND;
            float acc = 0.f;
#pragma unroll
            for (int q = 0; q < 16; q++)
                acc += wk[lane + 32 * q] * s_vec[lane + 32 * q];
#pragma unroll
            for (int off = 16; off; off >>= 1)
                acc += __shfl_xor_sync(0xffffffffu, acc, off);
            if (lane == 0) {
                const float kwv = acc + bk[f] * wsum;
                g_kw[b * NF + f] = kwv;
                s_kw32[warp * 4 + j] = bq[f] * kwv;
            }
        }
        __syncthreads();
        if (tid == 0) {
            float cp = 0.f;
#pragma unroll
            for (int i = 0; i < SL; i++) cp += s_kw32[i];     // smem-only chain
            g_cp[b * CH + c] = cp;
        }
    }
    BATCH_BAR(g_cnt3);

    // ---------------- Stage C: u slice (d in [c*32, c*32+32)) --------------
    {
        s_vec[tid]       = __ldcg(&g_kw[b * NF + tid]);
        s_vec[tid + 256] = __ldcg(&g_kw[b * NF + tid + 256]);
        __syncthreads();

        const int dl = tid & 31, fg = tid >> 5;     // fg: 0..7, 64 f each
        float acc = 0.f;
#pragma unroll
        for (int i = 0; i < 64; i++) {
            const int f = fg * 64 + i;
            acc += Wq[(size_t)f * ND + c * SL + dl] * s_vec[f];
        }
        __syncthreads();
        s_red[fg * SL + dl] = acc;
        __syncthreads();
        if (tid < SL) {
            float u = 0.f;
#pragma unroll
            for (int g2 = 0; g2 < 8; g2++) u += s_red[g2 * SL + tid];
            g_u[b * ND + c * SL + tid] = u;
        }
    }
    BATCH_BAR(g_cnt4);

    // ---------------- Stage D: pass2 on own x chunk (DRAM pass 2) ----------
    {
        if (tid < CH) s_cp[tid] = __ldcg(&g_cp[b * CH + tid]);  // parallel L2
        float4 u4[4];
        const float4* up = (const float4*)(g_u + b * ND);
#pragma unroll
        for (int j = 0; j < 4; j++) u4[j] = __ldcg(&up[32 * j + lane]);
        __syncthreads();

        float cb = 0.f;
#pragma unroll
        for (int k = 0; k < CH; k++) cb += s_cp[k];   // fixed order everywhere
        const float btv = bt[0];

        float4 acc[4] = {{0,0,0,0},{0,0,0,0},{0,0,0,0},{0,0,0,0}};
        float tsum = 0.f;

#pragma unroll 2
        for (int r = warp; r < ROWS; r += NW) {
            const float4* xp = (const float4*)x + ((size_t)b * NS + s0 + r) * (ND / 4);
            float4 xv[4];
#pragma unroll
            for (int j = 0; j < 4; j++) xv[j] = xp[32 * j + lane];
            float dot = 0.f;
#pragma unroll
            for (int j = 0; j < 4; j++)
                dot += xv[j].x * u4[j].x + xv[j].y * u4[j].y +
                       xv[j].z * u4[j].z + xv[j].w * u4[j].w;
#pragma unroll
            for (int off = 16; off; off >>= 1)
                dot += __shfl_xor_sync(0xffffffffu, dot, off);
            const float ta = (dot + cb) * INV_SQRT_DFF + btv;
            tsum += ta;
#pragma unroll
            for (int j = 0; j < 4; j++) {
                acc[j].x += ta * xv[j].x; acc[j].y += ta * xv[j].y;
                acc[j].z += ta * xv[j].z; acc[j].w += ta * xv[j].w;
            }
        }
#pragma unroll
        for (int j = 0; j < 4; j++) s4[warp * 128 + 32 * j + lane] = acc[j];
        if (lane == 0) s_T[warp] = tsum;
        __syncthreads();

        const float* s = (const float*)s4;
        float v0 = 0.f, v1 = 0.f;
#pragma unroll
        for (int w = 0; w < NW; w++) {
            v0 += s[w * 512 + tid];
            v1 += s[w * 512 + tid + 256];
        }
        float* dst = g_xtp + ((size_t)c * NB + b) * ND;
        dst[tid] = v0;
        dst[tid + 256] = v1;
        if (tid == 0) {
            float t = 0.f;
#pragma unroll
            for (int w = 0; w < NW; w++) t += s_T[w];
            g_Tp[c * NB + b] = t;
        }
    }

    // ---------------- Reset counters for next graph replay ------------------
    __threadfence();
    if (tid == 0) {
        const int old = atomicAdd(&g_fin[b], 1);
        if (old == CH - 1) {       // last arriver: nobody spins anymore
            g_cnt1[b] = 0; g_cnt2[b] = 0;
            g_cnt3[b] = 0; g_cnt4[b] = 0;
            g_fin[b] = 0;
        }
    }
}

// ---------------------------------------------------------------------------
// Reduce xt partials + T partials. grid 32, 512 threads (1 MB of traffic)
// ---------------------------------------------------------------------------
__global__ __launch_bounds__(512) void k_red2() {
    const int i = blockIdx.x * 512 + threadIdx.x;
    float v = 0.f;
#pragma unroll
    for (int c = 0; c < CH; c++) v += g_xtp[(size_t)c * NB * ND + i];
    g_xt[i] = v;

    if (blockIdx.x == 0 && threadIdx.x < NB) {
        float t = 0.f;
#pragma unroll
        for (int c = 0; c < CH; c++) t += g_Tp[c * NB + threadIdx.x];
        g_T[threadIdx.x] = t;
    }
}

// ---------------------------------------------------------------------------
// latent[b,f] = Wv[f,:].xt[b,:] + bv[f]*T[b]
// Batch-tiled: 32 blocks, each owns 16 f-rows of Wv in smem (Wv read ONCE).
// ---------------------------------------------------------------------------
__global__ __launch_bounds__(256) void k_out(const float* __restrict__ Wv,
                                             const float* __restrict__ bv,
                                             float* __restrict__ out) {
    const int f0 = blockIdx.x * 16;
    const int tid = threadIdx.x, warp = tid >> 5, lane = tid & 31;

    __shared__ float s_wv[16 * ND];     // 32 KB
    __shared__ float s_T[NB];

    {
        const float4* src = (const float4*)(Wv + (size_t)f0 * ND);
        float4* d4 = (float4*)s_wv;
#pragma unroll
        for (int i = 0; i < 8; i++) d4[tid + 256 * i] = src[tid + 256 * i];
    }
    if (tid < NB) s_T[tid] = g_T[tid];
    __syncthreads();

#pragma unroll
    for (int j = 0; j < 2; j++) {
        const int fl = warp * 2 + j;
        const int f  = f0 + fl;
        const float4* wrow = (const float4*)(s_wv + fl * ND);
        float4 w4[4];
#pragma unroll
        for (int q = 0; q < 4; q++) w4[q] = wrow[lane + 32 * q];
        const float bvf = bv[f];

#pragma unroll 4
        for (int b = 0; b < NB; b++) {
            const float4* xt4 = (const float4*)(g_xt + b * ND);
            float dot = 0.f;
#pragma unroll
            for (int q = 0; q < 4; q++) {
                float4 xv = xt4[lane + 32 * q];
                dot += w4[q].x * xv.x + w4[q].y * xv.y +
                       w4[q].z * xv.z + w4[q].w * xv.w;
            }
#pragma unroll
            for (int off = 16; off; off >>= 1)
                dot += __shfl_xor_sync(0xffffffffu, dot, off);
            if (lane == 0) out[b * NF + f] = dot + bvf * s_T[b];
        }
    }
}

// ---------------------------------------------------------------------------
extern "C" void kernel_launch(void* const* d_in, const int* in_sizes, int n_in,
                              void* d_out, int out_size) {
    const float* x  = (const float*)d_in[0];
    const float* Wq = (const float*)d_in[1];
    const float* bq = (const float*)d_in[2];
    const float* Wk = (const float*)d_in[3];
    const float* bk = (const float*)d_in[4];
    const float* Wv = (const float*)d_in[5];
    const float* bv = (const float*)d_in[6];
    const float* Wt = (const float*)d_in[7];
    const float* bt = (const float*)d_in[8];
    float* out = (float*)d_out;

    k_fused<<<NB * CH, 256>>>(x, Wq, bq, Wk, bk, Wt, bt);
    k_red2 <<<32, 512>>>();
    k_out  <<<32, 256>>>(Wv, bv, out);
}

// round 10
// speedup vs baseline: 2.3255x; 1.4731x over previous
#include <cuda_runtime.h>
#include <cstddef>

// Problem constants
constexpr int NB = 32;     // batch
constexpr int NS = 2048;   // sequence
constexpr int ND = 512;    // model dim
constexpr int NF = 512;    // dff
constexpr int C1 = 32;     // s-chunks for pass 1
constexpr int C2 = 32;     // s-chunks for pass 2
constexpr int NW = 8;      // warps per pass block (256 threads)
#define INV_SQRT_DFF 0.044194173824159216f  // 1/sqrt(512)

// Scratch (device globals; no allocation anywhere)
__device__ float g_xwp[C1 * NB * ND];   // xw partials per chunk
__device__ float g_xw[NB * ND];
__device__ float g_wsum;
__device__ float g_kw[NB * NF];         // kw row-major per batch
__device__ float g_cp[NB * 64];         // c partials per 8-f group, batch-major
__device__ float g_u[NB * ND];
__device__ float g_c[NB];
__device__ float g_xtp[C2 * NB * ND];   // xt partials
__device__ float g_xt[NB * ND];
__device__ float g_Tp[C2 * NB];
__device__ float g_T[NB];

// ---------------------------------------------------------------------------
// Pass 1: xw[b,d] = sum_s Wt[s] * x[b,s,d]   (streams 128 MB of x, ~7.5 TB/s)
// grid (NB, C1), 256 threads
// ---------------------------------------------------------------------------
__global__ __launch_bounds__(256) void k_xw(const float* __restrict__ x,
                                            const float* __restrict__ Wt) {
    const int b = blockIdx.x, c = blockIdx.y;
    const int tid = threadIdx.x, warp = tid >> 5, lane = tid & 31;
    const int rows = NS / C1;  // 64
    const int s0 = c * rows;

    __shared__ float s_wt[NS / C1];
    __shared__ float4 s4[NW * 128];

    if (tid < rows) s_wt[tid] = Wt[s0 + tid];
    __syncthreads();

    float4 acc[4] = {{0,0,0,0},{0,0,0,0},{0,0,0,0},{0,0,0,0}};
#pragma unroll 2
    for (int r = warp; r < rows; r += NW) {
        const float4* xp = (const float4*)x + ((size_t)b * NS + s0 + r) * (ND / 4);
        const float wt = s_wt[r];
#pragma unroll
        for (int j = 0; j < 4; j++) {
            float4 v = xp[32 * j + lane];
            acc[j].x += wt * v.x; acc[j].y += wt * v.y;
            acc[j].z += wt * v.z; acc[j].w += wt * v.w;
        }
    }
#pragma unroll
    for (int j = 0; j < 4; j++) s4[warp * 128 + 32 * j + lane] = acc[j];
    __syncthreads();

    const float* s = (const float*)s4;
    float v0 = 0.f, v1 = 0.f;
#pragma unroll
    for (int w = 0; w < NW; w++) {
        v0 += s[w * 512 + tid];
        v1 += s[w * 512 + tid + 256];
    }
    float* dst = g_xwp + ((size_t)c * NB + b) * ND;
    dst[tid] = v0;
    dst[tid + 256] = v1;
}

// ---------------------------------------------------------------------------
// Reduce xw partials; block 0 also computes wsum = sum(Wt)
// grid 32, 512 threads
// ---------------------------------------------------------------------------
__global__ __launch_bounds__(512) void k_red1(const float* __restrict__ Wt) {
    const int i = blockIdx.x * 512 + threadIdx.x;
    float v = 0.f;
#pragma unroll
    for (int c = 0; c < C1; c++) v += g_xwp[(size_t)c * NB * ND + i];
    g_xw[i] = v;

    if (blockIdx.x == 0) {
        __shared__ float sr[512];
        float w = 0.f;
        for (int k = threadIdx.x; k < NS; k += 512) w += Wt[k];
        sr[threadIdx.x] = w;
        __syncthreads();
        for (int off = 256; off; off >>= 1) {
            if (threadIdx.x < off) sr[threadIdx.x] += sr[threadIdx.x + off];
            __syncthreads();
        }
        if (threadIdx.x == 0) g_wsum = sr[0];
    }
}

// ---------------------------------------------------------------------------
// kw[b,f] = Wk[f,:].xw[b,:] + bk[f]*wsum   (warp per output)
// Also c partial: g_cp[b*64+group] = sum_{f in 8-group} bq[f]*kw[b,f]
// grid (NB, NF/8), 256 threads
// ---------------------------------------------------------------------------
__global__ __launch_bounds__(256) void k_kw(const float* __restrict__ Wk,
                                            const float* __restrict__ bk,
                                            const float* __restrict__ bq) {
    const int b = blockIdx.x;
    const int warp = threadIdx.x >> 5, lane = threadIdx.x & 31;
    const int f = blockIdx.y * 8 + warp;

    __shared__ float s_c[8];

    const float4* wk = (const float4*)Wk + (size_t)f * (ND / 4);
    const float4* xw = (const float4*)(g_xw + b * ND);
    float dot = 0.f;
#pragma unroll
    for (int q = 0; q < 4; q++) {
        float4 wv = wk[32 * q + lane];
        float4 xv = xw[32 * q + lane];
        dot += wv.x * xv.x + wv.y * xv.y + wv.z * xv.z + wv.w * xv.w;
    }
#pragma unroll
    for (int off = 16; off; off >>= 1) dot += __shfl_xor_sync(0xffffffffu, dot, off);
    if (lane == 0) {
        const float kwv = dot + bk[f] * g_wsum;
        g_kw[b * NF + f] = kwv;
        s_c[warp] = bq[f] * kwv;
    }
    __syncthreads();
    if (threadIdx.x == 0) {
        float cs = 0.f;
#pragma unroll
        for (int w = 0; w < 8; w++) cs += s_c[w];
        g_cp[b * 64 + blockIdx.y] = cs;
    }
}

// ---------------------------------------------------------------------------
// u[b,d-tile] = sum_f Wq[f,d]*kw[b,f]  — FULL f-sum per block (no ured).
// grid (16 d-tiles, NB) = 512 blocks, 512 threads (warp = 32-f group).
// Block (0,b) also reduces c[b] from g_cp (parallel loads -> smem chain).
// ---------------------------------------------------------------------------
__global__ __launch_bounds__(512) void k_u(const float* __restrict__ Wq) {
    const int d0 = blockIdx.x * 32;
    const int b  = blockIdx.y;
    const int tid = threadIdx.x;
    const int dl = tid & 31;       // lane = d within tile
    const int fg = tid >> 5;       // warp = f-group (16 groups x 32 f)

    __shared__ float s_kw[NF];
    __shared__ float s_red[512];
    __shared__ float s_c[64];

    s_kw[tid] = g_kw[b * NF + tid];
    if (blockIdx.x == 0 && tid < 64) s_c[tid] = g_cp[b * 64 + tid];
    __syncthreads();

    float acc = 0.f;
    const float* wq = Wq + (size_t)(fg * 32) * ND + d0 + dl;
#pragma unroll
    for (int i = 0; i < 32; i++)
        acc += wq[(size_t)i * ND] * s_kw[fg * 32 + i];   // coalesced + broadcast
    s_red[fg * 32 + dl] = acc;
    __syncthreads();

    if (tid < 32) {
        float u = 0.f;
#pragma unroll
        for (int g = 0; g < 16; g++) u += s_red[g * 32 + tid];
        g_u[b * ND + d0 + tid] = u;
    }
    if (blockIdx.x == 0 && tid == 0) {
        float cs = 0.f;
#pragma unroll
        for (int i = 0; i < 64; i++) cs += s_c[i];       // smem-only chain
        g_c[b] = cs;
    }
}

// ---------------------------------------------------------------------------
// Pass 2: ta[b,s] = (x[b,s].u[b] + c[b])/sqrt(DFF) + bt
//         xt[b,d] += ta*x[b,s,d] ; T[b] += ta      (streams 128 MB of x)
// grid (NB, C2), 256 threads
// ---------------------------------------------------------------------------
__global__ __launch_bounds__(256) void k_pass2(const float* __restrict__ x,
                                               const float* __restrict__ bt) {
    const int b = blockIdx.x, c = blockIdx.y;
    const int tid = threadIdx.x, warp = tid >> 5, lane = tid & 31;
    const int rows = NS / C2;  // 64
    const int s0 = c * rows;

    __shared__ float4 s4[NW * 128];
    __shared__ float s_T[NW];

    const float4* up = (const float4*)(g_u + b * ND);
    float4 u4[4];
#pragma unroll
    for (int j = 0; j < 4; j++) u4[j] = up[32 * j + lane];
    const float cb = g_c[b];
    const float btv = bt[0];

    float4 acc[4] = {{0,0,0,0},{0,0,0,0},{0,0,0,0},{0,0,0,0}};
    float tsum = 0.f;

#pragma unroll 2
    for (int r = warp; r < rows; r += NW) {
        const float4* xp = (const float4*)x + ((size_t)b * NS + s0 + r) * (ND / 4);
        float4 xv[4];
#pragma unroll
        for (int j = 0; j < 4; j++) xv[j] = xp[32 * j + lane];
        float dot = 0.f;
#pragma unroll
        for (int j = 0; j < 4; j++)
            dot += xv[j].x * u4[j].x + xv[j].y * u4[j].y +
                   xv[j].z * u4[j].z + xv[j].w * u4[j].w;
#pragma unroll
        for (int off = 16; off; off >>= 1) dot += __shfl_xor_sync(0xffffffffu, dot, off);
        const float ta = (dot + cb) * INV_SQRT_DFF + btv;
        tsum += ta;
#pragma unroll
        for (int j = 0; j < 4; j++) {
            acc[j].x += ta * xv[j].x; acc[j].y += ta * xv[j].y;
            acc[j].z += ta * xv[j].z; acc[j].w += ta * xv[j].w;
        }
    }
#pragma unroll
    for (int j = 0; j < 4; j++) s4[warp * 128 + 32 * j + lane] = acc[j];
    if (lane == 0) s_T[warp] = tsum;
    __syncthreads();

    const float* s = (const float*)s4;
    float v0 = 0.f, v1 = 0.f;
#pragma unroll
    for (int w = 0; w < NW; w++) {
        v0 += s[w * 512 + tid];
        v1 += s[w * 512 + tid + 256];
    }
    float* dst = g_xtp + ((size_t)c * NB + b) * ND;
    dst[tid] = v0;
    dst[tid + 256] = v1;
    if (tid == 0) {
        float t = 0.f;
#pragma unroll
        for (int w = 0; w < NW; w++) t += s_T[w];
        g_Tp[c * NB + b] = t;
    }
}

// ---------------------------------------------------------------------------
// Reduce xt partials + T partials. grid 32, 512 threads
// ---------------------------------------------------------------------------
__global__ __launch_bounds__(512) void k_red2() {
    const int i = blockIdx.x * 512 + threadIdx.x;
    float v = 0.f;
#pragma unroll
    for (int c = 0; c < C2; c++) v += g_xtp[(size_t)c * NB * ND + i];
    g_xt[i] = v;

    if (blockIdx.x == 0 && threadIdx.x < NB) {
        float t = 0.f;
#pragma unroll
        for (int c = 0; c < C2; c++) t += g_Tp[c * NB + threadIdx.x];
        g_T[threadIdx.x] = t;
    }
}

// ---------------------------------------------------------------------------
// latent[b,f] = Wv[f,:].xt[b,:] + bv[f]*T[b]
// grid (16 f-tiles, NB) = 512 blocks, 512 threads; xt[b] in smem;
// warp handles 2 f outputs (coalesced Wv + smem dot + shfl reduce).
// ---------------------------------------------------------------------------
__global__ __launch_bounds__(512) void k_out(const float* __restrict__ Wv,
                                             const float* __restrict__ bv,
                                             float* __restrict__ out) {
    const int f0 = blockIdx.x * 32;
    const int b  = blockIdx.y;
    const int tid = threadIdx.x, warp = tid >> 5, lane = tid & 31;

    __shared__ float s_xt[ND];
    __shared__ float s_Tb;

    s_xt[tid] = g_xt[b * ND + tid];
    if (tid == 0) s_Tb = g_T[b];
    __syncthreads();

    const float4* xt4 = (const float4*)s_xt;
    float4 x4[4];
#pragma unroll
    for (int q = 0; q < 4; q++) x4[q] = xt4[lane + 32 * q];
    const float Tb = s_Tb;

#pragma unroll
    for (int j = 0; j < 2; j++) {
        const int f = f0 + warp * 2 + j;
        const float4* wv = (const float4*)Wv + (size_t)f * (ND / 4);
        float dot = 0.f;
#pragma unroll
        for (int q = 0; q < 4; q++) {
            float4 w = wv[lane + 32 * q];
            dot += w.x * x4[q].x + w.y * x4[q].y + w.z * x4[q].z + w.w * x4[q].w;
        }
#pragma unroll
        for (int off = 16; off; off >>= 1)
            dot += __shfl_xor_sync(0xffffffffu, dot, off);
        if (lane == 0) out[b * NF + f] = dot + bv[f] * Tb;
    }
}

// ---------------------------------------------------------------------------
extern "C" void kernel_launch(void* const* d_in, const int* in_sizes, int n_in,
                              void* d_out, int out_size) {
    const float* x  = (const float*)d_in[0];
    const float* Wq = (const float*)d_in[1];
    const float* bq = (const float*)d_in[2];
    const float* Wk = (const float*)d_in[3];
    const float* bk = (const float*)d_in[4];
    const float* Wv = (const float*)d_in[5];
    const float* bv = (const float*)d_in[6];
    const float* Wt = (const float*)d_in[7];
    const float* bt = (const float*)d_in[8];
    float* out = (float*)d_out;

    k_xw   <<<dim3(NB, C1), 256>>>(x, Wt);
    k_red1 <<<32, 512>>>(Wt);
    k_kw   <<<dim3(NB, NF / 8), 256>>>(Wk, bk, bq);
    k_u    <<<dim3(16, NB), 512>>>(Wq);
    k_pass2<<<dim3(NB, C2), 256>>>(x, bt);
    k_red2 <<<32, 512>>>();
    k_out  <<<dim3(16, NB), 512>>>(Wv, bv, out);
}

// round 11
// speedup vs baseline: 2.3338x; 1.0035x over previous
#include <cuda_runtime.h>
#include <cstddef>

// Problem constants
constexpr int NB = 32;     // batch
constexpr int NS = 2048;   // sequence
constexpr int ND = 512;    // model dim
constexpr int NF = 512;    // dff
constexpr int C1 = 32;     // s-chunks for pass 1
constexpr int C2 = 32;     // s-chunks for pass 2
constexpr int NW = 8;      // warps per pass block (256 threads)
constexpr int MIDB = 512;  // blocks in k_mid / k_tail (co-resident)
#define INV_SQRT_DFF 0.044194173824159216f  // 1/sqrt(512)

// Scratch (device globals; statically zero-initialized, no allocation)
__device__ float g_xwp[C1 * NB * ND];   // xw partials (layout c*16384 + b*512 + d)
__device__ float g_xw[NB * ND];
__device__ float g_wsum;
__device__ float g_kw[NB * NF];
__device__ float g_cp[NB * 16];         // c partials per 32-f group
__device__ float g_u[NB * ND];
__device__ float g_c[NB];
__device__ float g_xtp[C2 * NB * ND];   // xt partials (same layout)
__device__ float g_xt[NB * ND];
__device__ float g_Tp[C2 * NB];
__device__ float g_T[NB];
__device__ int   g_mc1, g_mc2, g_mfin;  // k_mid barriers
__device__ int   g_tc1, g_tfin;         // k_tail barrier

// grid-wide spin barrier; ONLY safe when all blocks are co-resident
#define GRID_BAR(CNT)                                                  \
    do {                                                               \
        __threadfence();                                               \
        if (tid == 0) {                                                \
            atomicAdd(&CNT, 1);                                        \
            while (*((volatile int*)&CNT) < MIDB) __nanosleep(64);     \
        }                                                              \
        __syncthreads();                                               \
    } while (0)

// ---------------------------------------------------------------------------
// Pass 1: xw partials.  grid (NB, C1) = 1024, 256 threads. Barrier-free.
// ---------------------------------------------------------------------------
__global__ __launch_bounds__(256) void k_xw(const float* __restrict__ x,
                                            const float* __restrict__ Wt) {
    const int b = blockIdx.x, c = blockIdx.y;
    const int tid = threadIdx.x, warp = tid >> 5, lane = tid & 31;
    const int rows = NS / C1;  // 64
    const int s0 = c * rows;

    __shared__ float s_wt[NS / C1];
    __shared__ float4 s4[NW * 128];

    if (tid < rows) s_wt[tid] = Wt[s0 + tid];
    __syncthreads();

    float4 acc[4] = {{0,0,0,0},{0,0,0,0},{0,0,0,0},{0,0,0,0}};
#pragma unroll 2
    for (int r = warp; r < rows; r += NW) {
        const float4* xp = (const float4*)x + ((size_t)b * NS + s0 + r) * (ND / 4);
        const float wt = s_wt[r];
#pragma unroll
        for (int j = 0; j < 4; j++) {
            float4 v = xp[32 * j + lane];
            acc[j].x += wt * v.x; acc[j].y += wt * v.y;
            acc[j].z += wt * v.z; acc[j].w += wt * v.w;
        }
    }
#pragma unroll
    for (int j = 0; j < 4; j++) s4[warp * 128 + 32 * j + lane] = acc[j];
    __syncthreads();

    const float* s = (const float*)s4;
    float v0 = 0.f, v1 = 0.f;
#pragma unroll
    for (int w = 0; w < NW; w++) {
        v0 += s[w * 512 + tid];
        v1 += s[w * 512 + tid + 256];
    }
    float* dst = g_xwp + ((size_t)c * NB + b) * ND;
    dst[tid] = v0;
    dst[tid + 256] = v1;
}

// ---------------------------------------------------------------------------
// k_mid: 512 co-resident blocks, 256 threads, 2 grid barriers.
//   R: g_xw = reduce(g_xwp); block 0: wsum
//   K: kw[b,f] + c partials        (b = bid>>4, fg = bid&15 -> 32 f)
//   U: u[b, d-tile] full f-sum     (b = bid&31, dt = bid>>5 -> 32 d)
// ---------------------------------------------------------------------------
__global__ __launch_bounds__(256) void k_mid(
    const float* __restrict__ Wk, const float* __restrict__ bk,
    const float* __restrict__ bq, const float* __restrict__ Wq,
    const float* __restrict__ Wt) {
    const int bid = blockIdx.x;
    const int tid = threadIdx.x, warp = tid >> 5, lane = tid & 31;

    __shared__ float s_a[ND];    // xw / kw broadcast
    __shared__ float s_b[ND];    // reduce scratch

    // ---------------- Stage R: reduce xw partials (32 elems per block) -----
    {
        const int e = tid >> 3, pg = tid & 7;   // 32 elems x 8 groups
        const int idx = bid * 32 + e;           // flat b*ND+d index
        float v = 0.f;
#pragma unroll
        for (int k = 0; k < 4; k++)
            v += __ldcg(&g_xwp[(size_t)(pg * 4 + k) * (NB * ND) + idx]);
        s_a[tid] = v;
        if (bid == 0) {                         // wsum (uses s_b)
            float w = 0.f;
            for (int k = tid; k < NS; k += 256) w += Wt[k];
            s_b[tid] = w;
        }
        __syncthreads();
        if (tid < 32) {
            float r = 0.f;
#pragma unroll
            for (int g = 0; g < 8; g++) r += s_a[tid * 8 + g];
            g_xw[bid * 32 + tid] = r;
        }
        if (bid == 0 && warp == 0) {
            float w = 0.f;
#pragma unroll
            for (int g = 0; g < 8; g++) w += s_b[lane + 32 * g];
#pragma unroll
            for (int off = 16; off; off >>= 1)
                w += __shfl_xor_sync(0xffffffffu, w, off);
            if (lane == 0) g_wsum = w;
        }
    }
    GRID_BAR(g_mc1);

    // ---------------- Stage K: kw + c partials -----------------------------
    {
        const int b = bid >> 4, fg = bid & 15, f0 = fg * 32;
        s_a[tid]       = __ldcg(&g_xw[b * ND + tid]);
        s_a[tid + 256] = __ldcg(&g_xw[b * ND + tid + 256]);
        __syncthreads();

        const float wsum = g_wsum;
#pragma unroll
        for (int j = 0; j < 4; j++) {
            const int f = f0 + warp * 4 + j;
            const float* wk = Wk + (size_t)f * ND;
            float acc = 0.f;
#pragma unroll
            for (int q = 0; q < 16; q++)
                acc += wk[lane + 32 * q] * s_a[lane + 32 * q];
#pragma unroll
            for (int off = 16; off; off >>= 1)
                acc += __shfl_xor_sync(0xffffffffu, acc, off);
            if (lane == 0) {
                const float kwv = acc + bk[f] * wsum;
                g_kw[b * NF + f] = kwv;
                s_b[warp * 4 + j] = bq[f] * kwv;
            }
        }
        __syncthreads();
        if (tid == 0) {
            float cp = 0.f;
#pragma unroll
            for (int i = 0; i < 32; i++) cp += s_b[i];   // smem-only chain
            g_cp[b * 16 + fg] = cp;
        }
    }
    GRID_BAR(g_mc2);

    // ---------------- Stage U: u slice (32 d) full f-sum --------------------
    {
        const int b = bid & 31, dt = bid >> 5, d0 = dt * 32;
        s_a[tid]       = __ldcg(&g_kw[b * NF + tid]);
        s_a[tid + 256] = __ldcg(&g_kw[b * NF + tid + 256]);
        __syncthreads();

        const int fg = tid >> 5, dl = lane;       // 8 groups x 64 f
        float acc = 0.f;
        const float* wq = Wq + (size_t)(fg * 64) * ND + d0 + dl;
#pragma unroll
        for (int i = 0; i < 64; i++)
            acc += wq[(size_t)i * ND] * s_a[fg * 64 + i];
        s_b[fg * 32 + dl] = acc;
        __syncthreads();
        if (tid < 32) {
            float u = 0.f;
#pragma unroll
            for (int g = 0; g < 8; g++) u += s_b[g * 32 + tid];
            g_u[b * ND + d0 + tid] = u;
        }
        if (dt == 0 && warp == 0) {               // c[b] via shfl (parallel L2)
            float v = (lane < 16) ? __ldcg(&g_cp[b * 16 + lane]) : 0.f;
#pragma unroll
            for (int off = 16; off; off >>= 1)
                v += __shfl_xor_sync(0xffffffffu, v, off);
            if (lane == 0) g_c[b] = v;
        }
    }

    // ---------------- Reset barriers for next graph replay ------------------
    __threadfence();
    if (tid == 0) {
        const int old = atomicAdd(&g_mfin, 1);
        if (old == MIDB - 1) { g_mc1 = 0; g_mc2 = 0; g_mfin = 0; }
    }
}

// ---------------------------------------------------------------------------
// Pass 2: ta + xt/T partials. grid (NB, C2) = 1024, 256 threads. Barrier-free.
// ---------------------------------------------------------------------------
__global__ __launch_bounds__(256) void k_pass2(const float* __restrict__ x,
                                               const float* __restrict__ bt) {
    const int b = blockIdx.x, c = blockIdx.y;
    const int tid = threadIdx.x, warp = tid >> 5, lane = tid & 31;
    const int rows = NS / C2;  // 64
    const int s0 = c * rows;

    __shared__ float4 s4[NW * 128];
    __shared__ float s_T[NW];

    const float4* up = (const float4*)(g_u + b * ND);
    float4 u4[4];
#pragma unroll
    for (int j = 0; j < 4; j++) u4[j] = up[32 * j + lane];
    const float cb = g_c[b];
    const float btv = bt[0];

    float4 acc[4] = {{0,0,0,0},{0,0,0,0},{0,0,0,0},{0,0,0,0}};
    float tsum = 0.f;

#pragma unroll 2
    for (int r = warp; r < rows; r += NW) {
        const float4* xp = (const float4*)x + ((size_t)b * NS + s0 + r) * (ND / 4);
        float4 xv[4];
#pragma unroll
        for (int j = 0; j < 4; j++) xv[j] = xp[32 * j + lane];
        float dot = 0.f;
#pragma unroll
        for (int j = 0; j < 4; j++)
            dot += xv[j].x * u4[j].x + xv[j].y * u4[j].y +
                   xv[j].z * u4[j].z + xv[j].w * u4[j].w;
#pragma unroll
        for (int off = 16; off; off >>= 1) dot += __shfl_xor_sync(0xffffffffu, dot, off);
        const float ta = (dot + cb) * INV_SQRT_DFF + btv;
        tsum += ta;
#pragma unroll
        for (int j = 0; j < 4; j++) {
            acc[j].x += ta * xv[j].x; acc[j].y += ta * xv[j].y;
            acc[j].z += ta * xv[j].z; acc[j].w += ta * xv[j].w;
        }
    }
#pragma unroll
    for (int j = 0; j < 4; j++) s4[warp * 128 + 32 * j + lane] = acc[j];
    if (lane == 0) s_T[warp] = tsum;
    __syncthreads();

    const float* s = (const float*)s4;
    float v0 = 0.f, v1 = 0.f;
#pragma unroll
    for (int w = 0; w < NW; w++) {
        v0 += s[w * 512 + tid];
        v1 += s[w * 512 + tid + 256];
    }
    float* dst = g_xtp + ((size_t)c * NB + b) * ND;
    dst[tid] = v0;
    dst[tid + 256] = v1;
    if (tid == 0) {
        float t = 0.f;
#pragma unroll
        for (int w = 0; w < NW; w++) t += s_T[w];
        g_Tp[c * NB + b] = t;
    }
}

// ---------------------------------------------------------------------------
// k_tail: 512 co-resident blocks, 256 threads, 1 grid barrier.
//   E: g_xt = reduce(g_xtp); block 0: g_T = reduce(g_Tp)
//   F: out[b, 32-f slice]          (b = bid>>4, fg = bid&15)
// ---------------------------------------------------------------------------
__global__ __launch_bounds__(256) void k_tail(const float* __restrict__ Wv,
                                              const float* __restrict__ bv,
                                              float* __restrict__ out) {
    const int bid = blockIdx.x;
    const int tid = threadIdx.x, warp = tid >> 5, lane = tid & 31;

    __shared__ float s_a[ND];
    __shared__ float s_b[ND];

    // ---------------- Stage E: reduce xt partials (+T in block 0) ----------
    {
        const int e = tid >> 3, pg = tid & 7;
        const int idx = bid * 32 + e;
        float v = 0.f;
#pragma unroll
        for (int k = 0; k < 4; k++)
            v += __ldcg(&g_xtp[(size_t)(pg * 4 + k) * (NB * ND) + idx]);
        s_a[tid] = v;
        if (bid == 0) {                         // T reduce: 32 b x 8 groups
            const int bb = tid >> 3;
            float t = 0.f;
#pragma unroll
            for (int k = 0; k < 4; k++)
                t += __ldcg(&g_Tp[(pg * 4 + k) * NB + bb]);
            s_b[tid] = t;
        }
        __syncthreads();
        if (tid < 32) {
            float r = 0.f;
#pragma unroll
            for (int g = 0; g < 8; g++) r += s_a[tid * 8 + g];
            g_xt[bid * 32 + tid] = r;
        }
        if (bid == 0 && tid < 32) {
            float t = 0.f;
#pragma unroll
            for (int g = 0; g < 8; g++) t += s_b[tid * 8 + g];
            g_T[tid] = t;
        }
    }
    GRID_BAR(g_tc1);

    // ---------------- Stage F: out slice ------------------------------------
    {
        const int b = bid >> 4, fg = bid & 15, f0 = fg * 32;
        s_a[tid]       = __ldcg(&g_xt[b * ND + tid]);
        s_a[tid + 256] = __ldcg(&g_xt[b * ND + tid + 256]);
        __syncthreads();

        const float Tb = __ldcg(&g_T[b]);
#pragma unroll
        for (int j = 0; j < 4; j++) {
            const int f = f0 + warp * 4 + j;
            const float* wv = Wv + (size_t)f * ND;
            float acc = 0.f;
#pragma unroll
            for (int q = 0; q < 16; q++)
                acc += wv[lane + 32 * q] * s_a[lane + 32 * q];
#pragma unroll
            for (int off = 16; off; off >>= 1)
                acc += __shfl_xor_sync(0xffffffffu, acc, off);
            if (lane == 0) out[b * NF + f] = acc + bv[f] * Tb;
        }
    }

    // ---------------- Reset barrier for next graph replay -------------------
    __threadfence();
    if (tid == 0) {
        const int old = atomicAdd(&g_tfin, 1);
        if (old == MIDB - 1) { g_tc1 = 0; g_tfin = 0; }
    }
}

// ---------------------------------------------------------------------------
extern "C" void kernel_launch(void* const* d_in, const int* in_sizes, int n_in,
                              void* d_out, int out_size) {
    const float* x  = (const float*)d_in[0];
    const float* Wq = (const float*)d_in[1];
    const float* bq = (const float*)d_in[2];
    const float* Wk = (const float*)d_in[3];
    const float* bk = (const float*)d_in[4];
    const float* Wv = (const float*)d_in[5];
    const float* bv = (const float*)d_in[6];
    const float* Wt = (const float*)d_in[7];
    const float* bt = (const float*)d_in[8];
    float* out = (float*)d_out;

    k_xw   <<<dim3(NB, C1), 256>>>(x, Wt);
    k_mid  <<<MIDB, 256>>>(Wk, bk, bq, Wq, Wt);
    k_pass2<<<dim3(NB, C2), 256>>>(x, bt);
    k_tail <<<MIDB, 256>>>(Wv, bv, out);
}